// round 16
// baseline (speedup 1.0000x reference)
#include <cuda_runtime.h>
#include <cstdint>

#define T_TOK   2048
#define D_MODEL 1024
#define D_FF    4096
#define NEXP    8
#define NPAIR   (T_TOK * 2)

// ---------------- scratch (device globals; no allocations) ----------------
__device__ int   g_counts[NEXP];
__device__ int   g_list[NEXP][T_TOK];          // pair indices per expert
__device__ float g_pairw[NPAIR];               // combine weight per pair (t*2+k)
__device__ float g_h[(size_t)NPAIR * D_FF];    // 64 MB: h = silu(g)*u per pair
__device__ float g_y[(size_t)NPAIR * D_MODEL]; // 16 MB: y = h@Wd + bd per pair

// ---------------- init ----------------
__global__ void zero_counts_kernel() {
    if (threadIdx.x < NEXP) g_counts[threadIdx.x] = 0;
}

// ---------------- router: logits -> softmax -> top2 -> renorm -------------
__global__ __launch_bounds__(256) void router_kernel(
    const float* __restrict__ x, const float* __restrict__ Wr,
    const float* __restrict__ br)
{
    const int t = blockIdx.x;
    __shared__ float sx[D_MODEL];
    __shared__ float slog[NEXP];
    const int tid = threadIdx.x;
    for (int i = tid; i < D_MODEL; i += 256) sx[i] = x[t * D_MODEL + i];
    __syncthreads();
    const int w = tid >> 5, lane = tid & 31;
    float acc = 0.f;
    #pragma unroll 8
    for (int j = lane; j < D_MODEL; j += 32) acc += sx[j] * Wr[j * NEXP + w];
    #pragma unroll
    for (int o = 16; o; o >>= 1) acc += __shfl_xor_sync(0xffffffffu, acc, o);
    if (lane == 0) slog[w] = acc + br[w];
    __syncthreads();
    if (tid == 0) {
        float mx = slog[0];
        #pragma unroll
        for (int e = 1; e < NEXP; e++) mx = fmaxf(mx, slog[e]);
        float p[NEXP];
        #pragma unroll
        for (int e = 0; e < NEXP; e++) p[e] = __expf(slog[e] - mx);
        // top-2 (strict > keeps lowest index on ties, matching jax top_k)
        int e0 = 0; float v0 = p[0];
        #pragma unroll
        for (int e = 1; e < NEXP; e++) if (p[e] > v0) { v0 = p[e]; e0 = e; }
        int e1 = -1; float v1 = -1.f;
        #pragma unroll
        for (int e = 0; e < NEXP; e++)
            if (e != e0 && p[e] > v1) { v1 = p[e]; e1 = e; }
        const float s = v0 + v1;           // softmax denom cancels in renorm
        g_pairw[t * 2 + 0] = v0 / s;
        g_pairw[t * 2 + 1] = v1 / s;
        int s0 = atomicAdd(&g_counts[e0], 1);
        g_list[e0][s0] = t * 2;
        int s1 = atomicAdd(&g_counts[e1], 1);
        g_list[e1][s1] = t * 2 + 1;
    }
}

// ------------- fused gate+up grouped GEMM with token gather ---------------
// C tile 128(m: pairs) x 64(n: ff), K=1024, BK=16, 256 threads, 8x4 reg tile x2
__global__ __launch_bounds__(256) void gateup_kernel(
    const float* __restrict__ x,
    const float* __restrict__ Wg, const float* __restrict__ bgb,
    const float* __restrict__ Wu, const float* __restrict__ bub)
{
    const int e   = blockIdx.z;
    const int cnt = g_counts[e];
    const int m0  = blockIdx.y * 128;
    if (m0 >= cnt) return;
    const int n0  = blockIdx.x * 64;

    __shared__ float sA[16][128];
    __shared__ float sBg[16][64];
    __shared__ float sBu[16][64];
    __shared__ int   spair[128];
    __shared__ int   srow[128];

    const int tid = threadIdx.x;
    if (tid < 128) {
        const int m = m0 + tid;
        const int pr = (m < cnt) ? g_list[e][m] : -1;
        spair[tid] = pr;
        srow[tid]  = (pr >= 0) ? (pr >> 1) : 0;
    }
    __syncthreads();

    const int lm = tid >> 1;            // 0..127 (A load row)
    const int lk = (tid & 1) * 8;       // 0 or 8 (A load k base)
    const int bk = tid >> 4;            // 0..15  (B load k)
    const int bn = (tid & 15) * 4;      // 0..60  (B load n, float4)
    const int tx = (tid & 15) * 4;      // n base for compute
    const int ty = (tid >> 4) * 8;      // m base for compute

    const float* __restrict__ xrow = x + (size_t)srow[lm] * D_MODEL;
    const float* __restrict__ Bg = Wg + (size_t)e * D_MODEL * D_FF;
    const float* __restrict__ Bu = Wu + (size_t)e * D_MODEL * D_FF;

    float ag[8][4] = {}, au[8][4] = {};

    for (int k0 = 0; k0 < D_MODEL; k0 += 16) {
        float4 a0 = *(const float4*)(xrow + k0 + lk);
        float4 a1 = *(const float4*)(xrow + k0 + lk + 4);
        sA[lk + 0][lm] = a0.x; sA[lk + 1][lm] = a0.y;
        sA[lk + 2][lm] = a0.z; sA[lk + 3][lm] = a0.w;
        sA[lk + 4][lm] = a1.x; sA[lk + 5][lm] = a1.y;
        sA[lk + 6][lm] = a1.z; sA[lk + 7][lm] = a1.w;
        *(float4*)&sBg[bk][bn] = *(const float4*)(Bg + (size_t)(k0 + bk) * D_FF + n0 + bn);
        *(float4*)&sBu[bk][bn] = *(const float4*)(Bu + (size_t)(k0 + bk) * D_FF + n0 + bn);
        __syncthreads();
        #pragma unroll
        for (int kk = 0; kk < 16; kk++) {
            float4 av0 = *(const float4*)&sA[kk][ty];
            float4 av1 = *(const float4*)&sA[kk][ty + 4];
            float4 g4  = *(const float4*)&sBg[kk][tx];
            float4 u4  = *(const float4*)&sBu[kk][tx];
            float aa[8] = {av0.x, av0.y, av0.z, av0.w, av1.x, av1.y, av1.z, av1.w};
            float gg[4] = {g4.x, g4.y, g4.z, g4.w};
            float uu[4] = {u4.x, u4.y, u4.z, u4.w};
            #pragma unroll
            for (int i = 0; i < 8; i++)
                #pragma unroll
                for (int j = 0; j < 4; j++) {
                    ag[i][j] += aa[i] * gg[j];
                    au[i][j] += aa[i] * uu[j];
                }
        }
        __syncthreads();
    }

    float bgv[4], buv[4];
    #pragma unroll
    for (int j = 0; j < 4; j++) {
        bgv[j] = bgb[e * D_FF + n0 + tx + j];
        buv[j] = bub[e * D_FF + n0 + tx + j];
    }
    #pragma unroll
    for (int i = 0; i < 8; i++) {
        const int pr = spair[ty + i];
        if (pr < 0) continue;
        float* hdst = g_h + (size_t)pr * D_FF + n0 + tx;
        #pragma unroll
        for (int j = 0; j < 4; j++) {
            const float g = ag[i][j] + bgv[j];
            const float u = au[i][j] + buv[j];
            const float sg = g / (1.f + __expf(-g));   // silu
            hdst[j] = sg * u;
        }
    }
}

// ---------------- down grouped GEMM: y = h @ Wd + bd ----------------------
// C tile 128 x 64, K=4096, BK=16
__global__ __launch_bounds__(256) void down_kernel(
    const float* __restrict__ Wd, const float* __restrict__ bdb)
{
    const int e   = blockIdx.z;
    const int cnt = g_counts[e];
    const int m0  = blockIdx.y * 128;
    if (m0 >= cnt) return;
    const int n0  = blockIdx.x * 64;

    __shared__ float sA[16][128];
    __shared__ float sB[16][64];
    __shared__ int   spair[128];

    const int tid = threadIdx.x;
    if (tid < 128) {
        const int m = m0 + tid;
        spair[tid] = (m < cnt) ? g_list[e][m] : -1;
    }
    __syncthreads();

    const int lm = tid >> 1;
    const int lk = (tid & 1) * 8;
    const int bk = tid >> 4;
    const int bn = (tid & 15) * 4;
    const int tx = (tid & 15) * 4;
    const int ty = (tid >> 4) * 8;

    const int prA = spair[lm];
    const float* __restrict__ arow = g_h + (size_t)((prA >= 0) ? prA : 0) * D_FF;
    const float* __restrict__ B = Wd + (size_t)e * D_FF * D_MODEL;

    float acc[8][4] = {};

    for (int k0 = 0; k0 < D_FF; k0 += 16) {
        float4 a0 = *(const float4*)(arow + k0 + lk);
        float4 a1 = *(const float4*)(arow + k0 + lk + 4);
        sA[lk + 0][lm] = a0.x; sA[lk + 1][lm] = a0.y;
        sA[lk + 2][lm] = a0.z; sA[lk + 3][lm] = a0.w;
        sA[lk + 4][lm] = a1.x; sA[lk + 5][lm] = a1.y;
        sA[lk + 6][lm] = a1.z; sA[lk + 7][lm] = a1.w;
        *(float4*)&sB[bk][bn] = *(const float4*)(B + (size_t)(k0 + bk) * D_MODEL + n0 + bn);
        __syncthreads();
        #pragma unroll
        for (int kk = 0; kk < 16; kk++) {
            float4 av0 = *(const float4*)&sA[kk][ty];
            float4 av1 = *(const float4*)&sA[kk][ty + 4];
            float4 b4  = *(const float4*)&sB[kk][tx];
            float aa[8] = {av0.x, av0.y, av0.z, av0.w, av1.x, av1.y, av1.z, av1.w};
            float bb[4] = {b4.x, b4.y, b4.z, b4.w};
            #pragma unroll
            for (int i = 0; i < 8; i++)
                #pragma unroll
                for (int j = 0; j < 4; j++)
                    acc[i][j] += aa[i] * bb[j];
        }
        __syncthreads();
    }

    float bdv[4];
    #pragma unroll
    for (int j = 0; j < 4; j++) bdv[j] = bdb[e * D_MODEL + n0 + tx + j];
    #pragma unroll
    for (int i = 0; i < 8; i++) {
        const int pr = spair[ty + i];
        if (pr < 0) continue;
        float* ydst = g_y + (size_t)pr * D_MODEL + n0 + tx;
        #pragma unroll
        for (int j = 0; j < 4; j++) ydst[j] = acc[i][j] + bdv[j];
    }
}

// ---------------- combine: out[t] = w0*y[2t] + w1*y[2t+1] -----------------
__global__ void combine_kernel(float* __restrict__ out) {
    const int idx = blockIdx.x * blockDim.x + threadIdx.x;  // over T*D
    const int t = idx >> 10;
    const int d = idx & 1023;
    const float w0 = g_pairw[2 * t], w1 = g_pairw[2 * t + 1];
    out[idx] = w0 * g_y[(size_t)(2 * t) * D_MODEL + d]
             + w1 * g_y[(size_t)(2 * t + 1) * D_MODEL + d];
}

// ---------------------------------------------------------------------------
extern "C" void kernel_launch(void* const* d_in, const int* in_sizes, int n_in,
                              void* d_out, int out_size) {
    const float* x  = (const float*)d_in[0];
    const float* Wr = (const float*)d_in[1];
    const float* br = (const float*)d_in[2];
    const float* Wg = (const float*)d_in[3];
    const float* bg = (const float*)d_in[4];
    const float* Wu = (const float*)d_in[5];
    const float* bu = (const float*)d_in[6];
    const float* Wd = (const float*)d_in[7];
    const float* bd = (const float*)d_in[8];
    float* out = (float*)d_out;

    zero_counts_kernel<<<1, 32>>>();
    router_kernel<<<T_TOK, 256>>>(x, Wr, br);
    // gate+up: N tiles = 4096/64, M tiles = 2048/128 (max tokens per expert), E
    gateup_kernel<<<dim3(D_FF / 64, T_TOK / 128, NEXP), 256>>>(x, Wg, bg, Wu, bu);
    // down: N tiles = 1024/64
    down_kernel<<<dim3(D_MODEL / 64, T_TOK / 128, NEXP), 256>>>(Wd, bd);
    combine_kernel<<<(T_TOK * D_MODEL) / 256, 256>>>(out);
}

// round 17
// speedup vs baseline: 1.0006x; 1.0006x over previous
#include <cuda_runtime.h>
#include <cstdint>

#define T_TOK   2048
#define D_MODEL 1024
#define D_FF    4096
#define NEXP    8
#define NPAIR   (T_TOK * 2)

// ---------------- scratch (device globals; no allocations) ----------------
__device__ int   g_counts[NEXP];
__device__ int   g_list[NEXP][T_TOK];          // pair indices per expert
__device__ float g_pairw[NPAIR];               // combine weight per pair (t*2+k)
__device__ float g_h[(size_t)NPAIR * D_FF];    // 64 MB: h = silu(g)*u per pair
__device__ float g_y[(size_t)NPAIR * D_MODEL]; // 16 MB: y = h@Wd + bd per pair

// ---------------- init ----------------
__global__ void zero_counts_kernel() {
    if (threadIdx.x < NEXP) g_counts[threadIdx.x] = 0;
}

// ---------------- router: logits -> softmax -> top2 -> renorm -------------
__global__ __launch_bounds__(256) void router_kernel(
    const float* __restrict__ x, const float* __restrict__ Wr,
    const float* __restrict__ br)
{
    const int t = blockIdx.x;
    __shared__ float sx[D_MODEL];
    __shared__ float slog[NEXP];
    const int tid = threadIdx.x;
    for (int i = tid; i < D_MODEL; i += 256) sx[i] = x[t * D_MODEL + i];
    __syncthreads();
    const int w = tid >> 5, lane = tid & 31;
    float acc = 0.f;
    #pragma unroll 8
    for (int j = lane; j < D_MODEL; j += 32) acc += sx[j] * Wr[j * NEXP + w];
    #pragma unroll
    for (int o = 16; o; o >>= 1) acc += __shfl_xor_sync(0xffffffffu, acc, o);
    if (lane == 0) slog[w] = acc + br[w];
    __syncthreads();
    if (tid == 0) {
        float mx = slog[0];
        #pragma unroll
        for (int e = 1; e < NEXP; e++) mx = fmaxf(mx, slog[e]);
        float p[NEXP];
        #pragma unroll
        for (int e = 0; e < NEXP; e++) p[e] = __expf(slog[e] - mx);
        // top-2 (strict > keeps lowest index on ties, matching jax top_k)
        int e0 = 0; float v0 = p[0];
        #pragma unroll
        for (int e = 1; e < NEXP; e++) if (p[e] > v0) { v0 = p[e]; e0 = e; }
        int e1 = -1; float v1 = -1.f;
        #pragma unroll
        for (int e = 0; e < NEXP; e++)
            if (e != e0 && p[e] > v1) { v1 = p[e]; e1 = e; }
        const float s = v0 + v1;           // softmax denom cancels in renorm
        g_pairw[t * 2 + 0] = v0 / s;
        g_pairw[t * 2 + 1] = v1 / s;
        int s0 = atomicAdd(&g_counts[e0], 1);
        g_list[e0][s0] = t * 2;
        int s1 = atomicAdd(&g_counts[e1], 1);
        g_list[e1][s1] = t * 2 + 1;
    }
}

// ------------- fused gate+up grouped GEMM with token gather ---------------
// C tile 128(m: pairs) x 64(n: ff), K=1024, BK=16, 256 threads, 8x4 reg tile x2
__global__ __launch_bounds__(256) void gateup_kernel(
    const float* __restrict__ x,
    const float* __restrict__ Wg, const float* __restrict__ bgb,
    const float* __restrict__ Wu, const float* __restrict__ bub)
{
    const int e   = blockIdx.z;
    const int cnt = g_counts[e];
    const int m0  = blockIdx.y * 128;
    if (m0 >= cnt) return;
    const int n0  = blockIdx.x * 64;

    __shared__ float sA[16][128];
    __shared__ float sBg[16][64];
    __shared__ float sBu[16][64];
    __shared__ int   spair[128];
    __shared__ int   srow[128];

    const int tid = threadIdx.x;
    if (tid < 128) {
        const int m = m0 + tid;
        const int pr = (m < cnt) ? g_list[e][m] : -1;
        spair[tid] = pr;
        srow[tid]  = (pr >= 0) ? (pr >> 1) : 0;
    }
    __syncthreads();

    const int lm = tid >> 1;            // 0..127 (A load row)
    const int lk = (tid & 1) * 8;       // 0 or 8 (A load k base)
    const int bk = tid >> 4;            // 0..15  (B load k)
    const int bn = (tid & 15) * 4;      // 0..60  (B load n, float4)
    const int tx = (tid & 15) * 4;      // n base for compute
    const int ty = (tid >> 4) * 8;      // m base for compute

    const float* __restrict__ xrow = x + (size_t)srow[lm] * D_MODEL;
    const float* __restrict__ Bg = Wg + (size_t)e * D_MODEL * D_FF;
    const float* __restrict__ Bu = Wu + (size_t)e * D_MODEL * D_FF;

    float ag[8][4] = {}, au[8][4] = {};

    for (int k0 = 0; k0 < D_MODEL; k0 += 16) {
        float4 a0 = *(const float4*)(xrow + k0 + lk);
        float4 a1 = *(const float4*)(xrow + k0 + lk + 4);
        sA[lk + 0][lm] = a0.x; sA[lk + 1][lm] = a0.y;
        sA[lk + 2][lm] = a0.z; sA[lk + 3][lm] = a0.w;
        sA[lk + 4][lm] = a1.x; sA[lk + 5][lm] = a1.y;
        sA[lk + 6][lm] = a1.z; sA[lk + 7][lm] = a1.w;
        *(float4*)&sBg[bk][bn] = *(const float4*)(Bg + (size_t)(k0 + bk) * D_FF + n0 + bn);
        *(float4*)&sBu[bk][bn] = *(const float4*)(Bu + (size_t)(k0 + bk) * D_FF + n0 + bn);
        __syncthreads();
        #pragma unroll
        for (int kk = 0; kk < 16; kk++) {
            float4 av0 = *(const float4*)&sA[kk][ty];
            float4 av1 = *(const float4*)&sA[kk][ty + 4];
            float4 g4  = *(const float4*)&sBg[kk][tx];
            float4 u4  = *(const float4*)&sBu[kk][tx];
            float aa[8] = {av0.x, av0.y, av0.z, av0.w, av1.x, av1.y, av1.z, av1.w};
            float gg[4] = {g4.x, g4.y, g4.z, g4.w};
            float uu[4] = {u4.x, u4.y, u4.z, u4.w};
            #pragma unroll
            for (int i = 0; i < 8; i++)
                #pragma unroll
                for (int j = 0; j < 4; j++) {
                    ag[i][j] += aa[i] * gg[j];
                    au[i][j] += aa[i] * uu[j];
                }
        }
        __syncthreads();
    }

    float bgv[4], buv[4];
    #pragma unroll
    for (int j = 0; j < 4; j++) {
        bgv[j] = bgb[e * D_FF + n0 + tx + j];
        buv[j] = bub[e * D_FF + n0 + tx + j];
    }
    #pragma unroll
    for (int i = 0; i < 8; i++) {
        const int pr = spair[ty + i];
        if (pr < 0) continue;
        float* hdst = g_h + (size_t)pr * D_FF + n0 + tx;
        #pragma unroll
        for (int j = 0; j < 4; j++) {
            const float g = ag[i][j] + bgv[j];
            const float u = au[i][j] + buv[j];
            const float sg = g / (1.f + __expf(-g));   // silu
            hdst[j] = sg * u;
        }
    }
}

// ---------------- down grouped GEMM: y = h @ Wd + bd ----------------------
// C tile 128 x 64, K=4096, BK=16
__global__ __launch_bounds__(256) void down_kernel(
    const float* __restrict__ Wd, const float* __restrict__ bdb)
{
    const int e   = blockIdx.z;
    const int cnt = g_counts[e];
    const int m0  = blockIdx.y * 128;
    if (m0 >= cnt) return;
    const int n0  = blockIdx.x * 64;

    __shared__ float sA[16][128];
    __shared__ float sB[16][64];
    __shared__ int   spair[128];

    const int tid = threadIdx.x;
    if (tid < 128) {
        const int m = m0 + tid;
        spair[tid] = (m < cnt) ? g_list[e][m] : -1;
    }
    __syncthreads();

    const int lm = tid >> 1;
    const int lk = (tid & 1) * 8;
    const int bk = tid >> 4;
    const int bn = (tid & 15) * 4;
    const int tx = (tid & 15) * 4;
    const int ty = (tid >> 4) * 8;

    const int prA = spair[lm];
    const float* __restrict__ arow = g_h + (size_t)((prA >= 0) ? prA : 0) * D_FF;
    const float* __restrict__ B = Wd + (size_t)e * D_FF * D_MODEL;

    float acc[8][4] = {};

    for (int k0 = 0; k0 < D_FF; k0 += 16) {
        float4 a0 = *(const float4*)(arow + k0 + lk);
        float4 a1 = *(const float4*)(arow + k0 + lk + 4);
        sA[lk + 0][lm] = a0.x; sA[lk + 1][lm] = a0.y;
        sA[lk + 2][lm] = a0.z; sA[lk + 3][lm] = a0.w;
        sA[lk + 4][lm] = a1.x; sA[lk + 5][lm] = a1.y;
        sA[lk + 6][lm] = a1.z; sA[lk + 7][lm] = a1.w;
        *(float4*)&sB[bk][bn] = *(const float4*)(B + (size_t)(k0 + bk) * D_MODEL + n0 + bn);
        __syncthreads();
        #pragma unroll
        for (int kk = 0; kk < 16; kk++) {
            float4 av0 = *(const float4*)&sA[kk][ty];
            float4 av1 = *(const float4*)&sA[kk][ty + 4];
            float4 b4  = *(const float4*)&sB[kk][tx];
            float aa[8] = {av0.x, av0.y, av0.z, av0.w, av1.x, av1.y, av1.z, av1.w};
            float bb[4] = {b4.x, b4.y, b4.z, b4.w};
            #pragma unroll
            for (int i = 0; i < 8; i++)
                #pragma unroll
                for (int j = 0; j < 4; j++)
                    acc[i][j] += aa[i] * bb[j];
        }
        __syncthreads();
    }

    float bdv[4];
    #pragma unroll
    for (int j = 0; j < 4; j++) bdv[j] = bdb[e * D_MODEL + n0 + tx + j];
    #pragma unroll
    for (int i = 0; i < 8; i++) {
        const int pr = spair[ty + i];
        if (pr < 0) continue;
        float* ydst = g_y + (size_t)pr * D_MODEL + n0 + tx;
        #pragma unroll
        for (int j = 0; j < 4; j++) ydst[j] = acc[i][j] + bdv[j];
    }
}

// ---------------- combine: out[t] = w0*y[2t] + w1*y[2t+1] -----------------
__global__ void combine_kernel(float* __restrict__ out) {
    const int idx = blockIdx.x * blockDim.x + threadIdx.x;  // over T*D
    const int t = idx >> 10;
    const int d = idx & 1023;
    const float w0 = g_pairw[2 * t], w1 = g_pairw[2 * t + 1];
    out[idx] = w0 * g_y[(size_t)(2 * t) * D_MODEL + d]
             + w1 * g_y[(size_t)(2 * t + 1) * D_MODEL + d];
}

// ---------------------------------------------------------------------------
extern "C" void kernel_launch(void* const* d_in, const int* in_sizes, int n_in,
                              void* d_out, int out_size) {
    const float* x  = (const float*)d_in[0];
    const float* Wr = (const float*)d_in[1];
    const float* br = (const float*)d_in[2];
    const float* Wg = (const float*)d_in[3];
    const float* bg = (const float*)d_in[4];
    const float* Wu = (const float*)d_in[5];
    const float* bu = (const float*)d_in[6];
    const float* Wd = (const float*)d_in[7];
    const float* bd = (const float*)d_in[8];
    float* out = (float*)d_out;

    zero_counts_kernel<<<1, 32>>>();
    router_kernel<<<T_TOK, 256>>>(x, Wr, br);
    // gate+up: N tiles = 4096/64, M tiles = 2048/128 (max tokens per expert), E
    gateup_kernel<<<dim3(D_FF / 64, T_TOK / 128, NEXP), 256>>>(x, Wg, bg, Wu, bu);
    // down: N tiles = 1024/64
    down_kernel<<<dim3(D_MODEL / 64, T_TOK / 128, NEXP), 256>>>(Wd, bd);
    combine_kernel<<<(T_TOK * D_MODEL) / 256, 256>>>(out);
}